// round 2
// baseline (speedup 1.0000x reference)
#include <cuda_runtime.h>
#include <cuda_bf16.h>
#include <cstddef>
#include <cstdint>

#define T_STEPS 200
#define BATCH   4096
#define OBS     64
#define HID     128
#define NENC    50

#define RECON_ELEMS ((size_t)T_STEPS * BATCH * OBS)
#define ZM_ELEMS    ((size_t)BATCH * 3)

// Scratch (static device arrays; no runtime allocation)
__device__ float g_gi[(size_t)NENC * BATCH * 3 * HID];
__device__ float g_hlast[(size_t)BATCH * HID];
__device__ float g_z0[(size_t)BATCH * 3];

__device__ __forceinline__ float fsigmoid(float x) {
    return __fdividef(1.0f, 1.0f + __expf(-x));
}
__device__ __forceinline__ float ftanh(float x) {
    return 1.0f - __fdividef(2.0f, __expf(2.0f * x) + 1.0f);
}

// ===========================================================================
// Kernel 1: GI = obs[:50] @ Wih^T + bih  (NT SGEMM M=204800, N=384, K=64)
// ===========================================================================
__global__ void gi_gemm_kernel(const float* __restrict__ A,
                               const float* __restrict__ B,
                               const float* __restrict__ bias)
{
    __shared__ float As[16][128];
    __shared__ float Bs[16][128];
    const int tid = threadIdx.x;
    const int bm = blockIdx.x * 128;
    const int bn = blockIdx.y * 128;
    const int tx = tid & 15;
    const int ty = tid >> 4;

    float acc[8][8];
#pragma unroll
    for (int i = 0; i < 8; ++i)
#pragma unroll
        for (int j = 0; j < 8; ++j) acc[i][j] = 0.0f;

    for (int kk = 0; kk < 64; kk += 16) {
#pragma unroll
        for (int l = 0; l < 2; ++l) {
            int fi = tid + 256 * l;
            int row = fi >> 2;
            int kq = fi & 3;
            float4 va = *(const float4*)(A + (size_t)(bm + row) * 64 + kk + kq * 4);
            As[kq * 4 + 0][row] = va.x; As[kq * 4 + 1][row] = va.y;
            As[kq * 4 + 2][row] = va.z; As[kq * 4 + 3][row] = va.w;
            float4 vb = *(const float4*)(B + (size_t)(bn + row) * 64 + kk + kq * 4);
            Bs[kq * 4 + 0][row] = vb.x; Bs[kq * 4 + 1][row] = vb.y;
            Bs[kq * 4 + 2][row] = vb.z; Bs[kq * 4 + 3][row] = vb.w;
        }
        __syncthreads();
#pragma unroll
        for (int k = 0; k < 16; ++k) {
            float4 a0 = *(const float4*)&As[k][ty * 8];
            float4 a1 = *(const float4*)&As[k][ty * 8 + 4];
            float4 b0 = *(const float4*)&Bs[k][tx * 8];
            float4 b1 = *(const float4*)&Bs[k][tx * 8 + 4];
            float ar[8] = {a0.x, a0.y, a0.z, a0.w, a1.x, a1.y, a1.z, a1.w};
            float br[8] = {b0.x, b0.y, b0.z, b0.w, b1.x, b1.y, b1.z, b1.w};
#pragma unroll
            for (int i = 0; i < 8; ++i)
#pragma unroll
                for (int j = 0; j < 8; ++j)
                    acc[i][j] = fmaf(ar[i], br[j], acc[i][j]);
        }
        __syncthreads();
    }

    float bb[8];
#pragma unroll
    for (int j = 0; j < 8; ++j) bb[j] = bias[bn + tx * 8 + j];
#pragma unroll
    for (int i = 0; i < 8; ++i) {
        size_t rbase = (size_t)(bm + ty * 8 + i) * 384 + bn + tx * 8;
        float4 v0 = make_float4(acc[i][0] + bb[0], acc[i][1] + bb[1],
                                acc[i][2] + bb[2], acc[i][3] + bb[3]);
        float4 v1 = make_float4(acc[i][4] + bb[4], acc[i][5] + bb[5],
                                acc[i][6] + bb[6], acc[i][7] + bb[7]);
        *(float4*)(g_gi + rbase)     = v0;
        *(float4*)(g_gi + rbase + 4) = v1;
    }
}

// ===========================================================================
// Kernel 2: persistent GRU. Block owns 32 batch rows for all 50 steps.
// Whh^T (192KB) + h (16KB) in smem. 256 threads: ug in [0,32) -> 4 units,
// rg in [0,8) -> 4 rows.
// ===========================================================================
#define GRU_SMEM_BYTES ((3 * 128 * 128 + 32 * 128) * 4)

#define GRU_ACC4(A, W) \
    A[r][0] = fmaf(hv, W.x, A[r][0]); A[r][1] = fmaf(hv, W.y, A[r][1]); \
    A[r][2] = fmaf(hv, W.z, A[r][2]); A[r][3] = fmaf(hv, W.w, A[r][3]);

#define GRU_COMP(CC, GRc, GZc, GNc, HOc, HNc) {                           \
    float rr = fsigmoid(GRc + aR[r][CC] + bR[CC]);                        \
    float zz = fsigmoid(GZc + aZ[r][CC] + bZ[CC]);                        \
    float nn = ftanh(GNc + rr * (aN[r][CC] + bN[CC]));                    \
    HNc = fmaf(zz, HOc - nn, nn); }

__global__ void __launch_bounds__(256) gru_kernel(const float* __restrict__ Whh,
                                                  const float* __restrict__ bhh)
{
    extern __shared__ float sm[];
    float* WT = sm;                   // [g*128+k][u]
    float* hs = sm + 3 * 128 * 128;   // [32][128]
    const int tid = threadIdx.x;

    for (int idx = tid; idx < 3 * 128 * 128; idx += 256) {
        int row = idx >> 7;
        int k = idx & 127;
        int g = row >> 7, u = row & 127;
        WT[(g * 128 + k) * 128 + u] = Whh[idx];
    }
    for (int idx = tid; idx < 32 * 128; idx += 256) hs[idx] = 0.0f;
    __syncthreads();

    const int ug = tid & 31;
    const int rg = tid >> 5;
    const int row0 = blockIdx.x * 32;

    float bR[4], bZ[4], bN[4];
#pragma unroll
    for (int c = 0; c < 4; ++c) {
        bR[c] = bhh[ug * 4 + c];
        bZ[c] = bhh[128 + ug * 4 + c];
        bN[c] = bhh[256 + ug * 4 + c];
    }
    const float4* Wr4 = (const float4*)(WT);
    const float4* Wz4 = (const float4*)(WT + 128 * 128);
    const float4* Wn4 = (const float4*)(WT + 2 * 128 * 128);

    for (int t = 0; t < NENC; ++t) {
        float aR[4][4], aZ[4][4], aN[4][4];
#pragma unroll
        for (int r = 0; r < 4; ++r)
#pragma unroll
            for (int c = 0; c < 4; ++c) { aR[r][c] = 0.f; aZ[r][c] = 0.f; aN[r][c] = 0.f; }

#pragma unroll 2
        for (int k = 0; k < 128; ++k) {
            float4 wr = Wr4[k * 32 + ug];
            float4 wz = Wz4[k * 32 + ug];
            float4 wn = Wn4[k * 32 + ug];
#pragma unroll
            for (int r = 0; r < 4; ++r) {
                float hv = hs[(rg * 4 + r) * 128 + k];
                GRU_ACC4(aR, wr)
                GRU_ACC4(aZ, wz)
                GRU_ACC4(aN, wn)
            }
        }
        __syncthreads();

        const float* gbase = g_gi + ((size_t)t * BATCH + row0) * 384;
#pragma unroll
        for (int r = 0; r < 4; ++r) {
            int lr = rg * 4 + r;
            const float4* gf = (const float4*)(gbase + (size_t)lr * 384);
            float4 giR = gf[ug];
            float4 giZ = gf[32 + ug];
            float4 giN = gf[64 + ug];
            float4 hold = ((const float4*)(hs + lr * 128))[ug];
            float4 hn;
            GRU_COMP(0, giR.x, giZ.x, giN.x, hold.x, hn.x)
            GRU_COMP(1, giR.y, giZ.y, giN.y, hold.y, hn.y)
            GRU_COMP(2, giR.z, giZ.z, giN.z, hold.z, hn.z)
            GRU_COMP(3, giR.w, giZ.w, giN.w, hold.w, hn.w)
            ((float4*)(hs + lr * 128))[ug] = hn;
        }
        __syncthreads();
    }

    for (int idx = tid; idx < 32 * 128; idx += 256)
        g_hlast[(size_t)row0 * 128 + idx] = hs[idx];
}

// ===========================================================================
// Kernel 3: z0 head (one thread per batch row)
// ===========================================================================
__global__ void z0_kernel(const float* __restrict__ eps,
                          const float* __restrict__ meanW, const float* __restrict__ meanb,
                          const float* __restrict__ logW, const float* __restrict__ logb,
                          float* __restrict__ omean, float* __restrict__ ologv)
{
    const int b = blockIdx.x * 128 + threadIdx.x;
    const float4* h4 = (const float4*)(g_hlast + (size_t)b * 128);
    float m0 = 0.f, m1 = 0.f, m2 = 0.f, l0 = 0.f, l1 = 0.f, l2 = 0.f;
#pragma unroll
    for (int i = 0; i < 32; ++i) {
        float4 h = h4[i];
        float4 w;
        w = ((const float4*)meanW)[i];
        m0 = fmaf(h.x, w.x, fmaf(h.y, w.y, fmaf(h.z, w.z, fmaf(h.w, w.w, m0))));
        w = ((const float4*)(meanW + 128))[i];
        m1 = fmaf(h.x, w.x, fmaf(h.y, w.y, fmaf(h.z, w.z, fmaf(h.w, w.w, m1))));
        w = ((const float4*)(meanW + 256))[i];
        m2 = fmaf(h.x, w.x, fmaf(h.y, w.y, fmaf(h.z, w.z, fmaf(h.w, w.w, m2))));
        w = ((const float4*)logW)[i];
        l0 = fmaf(h.x, w.x, fmaf(h.y, w.y, fmaf(h.z, w.z, fmaf(h.w, w.w, l0))));
        w = ((const float4*)(logW + 128))[i];
        l1 = fmaf(h.x, w.x, fmaf(h.y, w.y, fmaf(h.z, w.z, fmaf(h.w, w.w, l1))));
        w = ((const float4*)(logW + 256))[i];
        l2 = fmaf(h.x, w.x, fmaf(h.y, w.y, fmaf(h.z, w.z, fmaf(h.w, w.w, l2))));
    }
    m0 += meanb[0]; m1 += meanb[1]; m2 += meanb[2];
    l0 += logb[0];  l1 += logb[1];  l2 += logb[2];
    omean[b * 3 + 0] = m0; omean[b * 3 + 1] = m1; omean[b * 3 + 2] = m2;
    ologv[b * 3 + 0] = l0; ologv[b * 3 + 1] = l1; ologv[b * 3 + 2] = l2;
    g_z0[b * 3 + 0] = fmaf(eps[b * 3 + 0], expf(0.5f * l0), m0);
    g_z0[b * 3 + 1] = fmaf(eps[b * 3 + 1], expf(0.5f * l1), m1);
    g_z0[b * 3 + 2] = fmaf(eps[b * 3 + 2], expf(0.5f * l2), m2);
}

// ===========================================================================
// Kernel 4: RK4 ODE + fused decoder. 64 thr/block, 16 elems/block,
// 4 threads/element (q owns 25 hidden units; j-side padded to 28 for float4).
// ===========================================================================
// smem float offsets
#define O_W1B 0        // 100 float4 (W1 row, b1)
#define O_W3  400      // 112 float4 (padded-j W3 cols, pad 0)
#define O_DW1 848      // 64 float4 (decW1 row, decb1)
#define O_W2  1104     // 100*112 floats: [k][pj] = W2[rj][k], pad 0
#define O_DW2 12304    // 64*64 floats: [k][oo] = decW2[oo][k]
#define O_B2P 16400    // 112 floats padded b2
#define O_DB2 16512    // 64
#define O_TS  16576    // 200
#define O_H1  16776    // 16*100
#define O_HD  18376    // 16*64
#define ODE_SMEM_BYTES (19400 * 4)

__device__ __forceinline__ void dynf(float zx, float zy, float zz,
    float& ox, float& oy, float& oz,
    const float4* sW1b, const float4* sW2T4, const float4* sW3,
    const float4* sB2p4, float* myH1, int q,
    float b3x, float b3y, float b3z)
{
#pragma unroll
    for (int j = 0; j < 25; ++j) {
        float4 w = sW1b[q * 25 + j];
        myH1[q * 25 + j] = ftanh(fmaf(zx, w.x, fmaf(zy, w.y, fmaf(zz, w.z, w.w))));
    }
    __syncwarp();
    float4 a[7];
#pragma unroll
    for (int i = 0; i < 7; ++i) a[i] = sB2p4[q * 7 + i];
#pragma unroll 4
    for (int k = 0; k < 100; ++k) {
        float hv = myH1[k];
        const float4* wrow = sW2T4 + k * 28 + q * 7;
#pragma unroll
        for (int i = 0; i < 7; ++i) {
            float4 w = wrow[i];
            a[i].x = fmaf(hv, w.x, a[i].x);
            a[i].y = fmaf(hv, w.y, a[i].y);
            a[i].z = fmaf(hv, w.z, a[i].z);
            a[i].w = fmaf(hv, w.w, a[i].w);
        }
    }
    __syncwarp();
    float px = 0.f, py = 0.f, pz = 0.f;
#pragma unroll
    for (int i = 0; i < 7; ++i) {
        float av[4] = {a[i].x, a[i].y, a[i].z, a[i].w};
#pragma unroll
        for (int c = 0; c < 4; ++c) {
            float h2 = ftanh(av[c]);
            float4 w3 = sW3[q * 28 + i * 4 + c];
            px = fmaf(h2, w3.x, px);
            py = fmaf(h2, w3.y, py);
            pz = fmaf(h2, w3.z, pz);
        }
    }
    px += __shfl_xor_sync(0xffffffffu, px, 1);
    px += __shfl_xor_sync(0xffffffffu, px, 2);
    py += __shfl_xor_sync(0xffffffffu, py, 1);
    py += __shfl_xor_sync(0xffffffffu, py, 2);
    pz += __shfl_xor_sync(0xffffffffu, pz, 1);
    pz += __shfl_xor_sync(0xffffffffu, pz, 2);
    ox = px + b3x; oy = py + b3y; oz = pz + b3z;
}

__global__ void __launch_bounds__(64) ode_kernel(
    const float* __restrict__ dynW1, const float* __restrict__ dynb1,
    const float* __restrict__ dynW2, const float* __restrict__ dynb2,
    const float* __restrict__ dynW3, const float* __restrict__ dynb3,
    const float* __restrict__ decW1, const float* __restrict__ decb1,
    const float* __restrict__ decW2, const float* __restrict__ decb2,
    const float* __restrict__ tsg,
    float* __restrict__ recon, float* __restrict__ traj)
{
    extern __shared__ float sm[];
    float4* sW1b  = (float4*)(sm + O_W1B);
    float4* sW3   = (float4*)(sm + O_W3);
    float4* sDW1  = (float4*)(sm + O_DW1);
    float*  sW2f  = sm + O_W2;
    float*  sDW2f = sm + O_DW2;
    float*  sB2p  = sm + O_B2P;
    float*  sDB2  = sm + O_DB2;
    float*  sTS   = sm + O_TS;

    const int tid = threadIdx.x;
    // ---- stage weights ----
    for (int i = tid; i < 100; i += 64)
        sW1b[i] = make_float4(dynW1[i * 3], dynW1[i * 3 + 1], dynW1[i * 3 + 2], dynb1[i]);
    for (int i = tid; i < 112; i += 64) {
        int ch = i / 28, off = i % 28;
        if (off < 25) {
            int rj = ch * 25 + off;
            sW3[i] = make_float4(dynW3[rj], dynW3[100 + rj], dynW3[200 + rj], 0.f);
            sB2p[i] = dynb2[rj];
        } else {
            sW3[i] = make_float4(0.f, 0.f, 0.f, 0.f);
            sB2p[i] = 0.f;
        }
    }
    for (int i = tid; i < 64; i += 64) {
        sDW1[i] = make_float4(decW1[i * 3], decW1[i * 3 + 1], decW1[i * 3 + 2], decb1[i]);
        sDB2[i] = decb2[i];
    }
    for (int idx = tid; idx < 100 * 112; idx += 64) {
        int k = idx / 112, p = idx % 112;
        int ch = p / 28, off = p % 28;
        sW2f[idx] = (off < 25) ? dynW2[(ch * 25 + off) * 100 + k] : 0.f;
    }
    for (int idx = tid; idx < 64 * 64; idx += 64) {
        int k = idx >> 6, oo = idx & 63;
        sDW2f[idx] = decW2[oo * 64 + k];
    }
    for (int i = tid; i < 200; i += 64) sTS[i] = tsg[i];
    __syncthreads();

    const int q = tid & 3;
    const int e = tid >> 2;
    const int b = blockIdx.x * 16 + e;
    float* myH1 = sm + O_H1 + e * 100;
    float* myHD = sm + O_HD + e * 64;
    const float4* sW2T4  = (const float4*)sW2f;
    const float4* sDW2_4 = (const float4*)sDW2f;
    const float4* sB2p4  = (const float4*)sB2p;
    const float4* sDB2_4 = (const float4*)sDB2;

    const float b3x = dynb3[0], b3y = dynb3[1], b3z = dynb3[2];

    float zx = g_z0[b * 3 + 0];
    float zy = g_z0[b * 3 + 1];
    float zz = g_z0[b * 3 + 2];

    for (int t = 0; t < T_STEPS; ++t) {
        if (q == 0) {
            size_t to = ((size_t)t * BATCH + b) * 3;
            traj[to] = zx; traj[to + 1] = zy; traj[to + 2] = zz;
        }
        // ---- decoder ----
        {
#pragma unroll
            for (int j = 0; j < 16; ++j) {
                float4 w = sDW1[q * 16 + j];
                float v = fmaf(zx, w.x, fmaf(zy, w.y, fmaf(zz, w.z, w.w)));
                myHD[q * 16 + j] = fmaxf(v, 0.f);
            }
            __syncwarp();
            float4 od[4];
#pragma unroll
            for (int i = 0; i < 4; ++i) od[i] = sDB2_4[q * 4 + i];
#pragma unroll 4
            for (int k = 0; k < 64; ++k) {
                float hv = myHD[k];
                const float4* wrow = sDW2_4 + k * 16 + q * 4;
#pragma unroll
                for (int i = 0; i < 4; ++i) {
                    float4 w = wrow[i];
                    od[i].x = fmaf(hv, w.x, od[i].x);
                    od[i].y = fmaf(hv, w.y, od[i].y);
                    od[i].z = fmaf(hv, w.z, od[i].z);
                    od[i].w = fmaf(hv, w.w, od[i].w);
                }
            }
            __syncwarp();
            float4* dst = (float4*)(recon + ((size_t)t * BATCH + b) * 64 + q * 16);
            dst[0] = od[0]; dst[1] = od[1]; dst[2] = od[2]; dst[3] = od[3];
        }
        // ---- RK4 step ----
        if (t < T_STEPS - 1) {
            float dt = sTS[t + 1] - sTS[t];
            float hh = 0.5f * dt;
            float k1x, k1y, k1z, k2x, k2y, k2z, k3x, k3y, k3z, k4x, k4y, k4z;
            dynf(zx, zy, zz, k1x, k1y, k1z, sW1b, sW2T4, sW3, sB2p4, myH1, q, b3x, b3y, b3z);
            dynf(fmaf(hh, k1x, zx), fmaf(hh, k1y, zy), fmaf(hh, k1z, zz),
                 k2x, k2y, k2z, sW1b, sW2T4, sW3, sB2p4, myH1, q, b3x, b3y, b3z);
            dynf(fmaf(hh, k2x, zx), fmaf(hh, k2y, zy), fmaf(hh, k2z, zz),
                 k3x, k3y, k3z, sW1b, sW2T4, sW3, sB2p4, myH1, q, b3x, b3y, b3z);
            dynf(fmaf(dt, k3x, zx), fmaf(dt, k3y, zy), fmaf(dt, k3z, zz),
                 k4x, k4y, k4z, sW1b, sW2T4, sW3, sB2p4, myH1, q, b3x, b3y, b3z);
            float s = dt * (1.0f / 6.0f);
            zx += s * (k1x + 2.0f * (k2x + k3x) + k4x);
            zy += s * (k1y + 2.0f * (k2y + k3y) + k4y);
            zz += s * (k1z + 2.0f * (k2z + k3z) + k4z);
        }
    }
}

// ===========================================================================
extern "C" void kernel_launch(void* const* d_in, const int* in_sizes, int n_in,
                              void* d_out, int out_size) {
    (void)in_sizes; (void)n_in; (void)out_size;
    const float* obs   = (const float*)d_in[0];
    const float* eps   = (const float*)d_in[1];
    const float* Wih   = (const float*)d_in[2];
    const float* Whh   = (const float*)d_in[3];
    const float* bih   = (const float*)d_in[4];
    const float* bhh   = (const float*)d_in[5];
    const float* meanW = (const float*)d_in[6];
    const float* meanb = (const float*)d_in[7];
    const float* logW  = (const float*)d_in[8];
    const float* logb  = (const float*)d_in[9];
    const float* dynW1 = (const float*)d_in[10];
    const float* dynb1 = (const float*)d_in[11];
    const float* dynW2 = (const float*)d_in[12];
    const float* dynb2 = (const float*)d_in[13];
    const float* dynW3 = (const float*)d_in[14];
    const float* dynb3 = (const float*)d_in[15];
    const float* decW1 = (const float*)d_in[16];
    const float* decb1 = (const float*)d_in[17];
    const float* decW2 = (const float*)d_in[18];
    const float* decb2 = (const float*)d_in[19];
    const float* ts    = (const float*)d_in[20];

    float* out   = (float*)d_out;
    float* recon = out;                      // [200,4096,64]
    float* omean = out + RECON_ELEMS;        // [4096,3]
    float* ologv = omean + ZM_ELEMS;         // [4096,3]
    float* traj  = ologv + ZM_ELEMS;         // [200,4096,3]

    cudaFuncSetAttribute(gru_kernel, cudaFuncAttributeMaxDynamicSharedMemorySize, GRU_SMEM_BYTES);
    cudaFuncSetAttribute(ode_kernel, cudaFuncAttributeMaxDynamicSharedMemorySize, ODE_SMEM_BYTES);

    dim3 g1(1600, 3);
    gi_gemm_kernel<<<g1, 256>>>(obs, Wih, bih);
    gru_kernel<<<128, 256, GRU_SMEM_BYTES>>>(Whh, bhh);
    z0_kernel<<<32, 128>>>(eps, meanW, meanb, logW, logb, omean, ologv);
    ode_kernel<<<256, 64, ODE_SMEM_BYTES>>>(dynW1, dynb1, dynW2, dynb2, dynW3, dynb3,
                                            decW1, decb1, decW2, decb2, ts, recon, traj);
}